// round 17
// baseline (speedup 1.0000x reference)
#include <cuda_runtime.h>
#include <cuda_bf16.h>

#define HID    64
#define ENC_T  20
#define DEC_T  30
#define TB     128
#define NTH    512
#define AROW   88           // bf16 cols per row of A/h buffer (bank-safe stride)
#define XROW   41           // x row stride in f32 (conflict-free)
#define TOT_T  (ENC_T + DEC_T)
#define STAG   2600         // per-group phase stagger (cycles)

typedef unsigned int u32;
typedef unsigned long long u64;

// ---- smem byte offsets ----
#define OFF_BHI   0                       // B frags hi: 4096 u64 = 32768 B
#define OFF_BLO   32768                   // 32768 B
#define OFF_HA    65536                   // h/A: 2 bufs x 2 parts x 128 x 88 bf16
#define HA_BUF    45056
#define HA_PART   22528
#define OFF_X     (OFF_HA + 2*HA_BUF)     // x: 128 x 41 f32 = 20992 B
#define OFF_WPOS  (OFF_X + 128*XROW*4)    // 128 f32
#define OFF_BPOS  (OFF_WPOS + 512)        // 2 f32 (+pad)
#define OFF_BTAB  (OFF_BPOS + 16)         // bias table: 256 f32
#define OFF_XW0   (OFF_BTAB + 1024)       // 256 f32
#define OFF_XW1   (OFF_XW0 + 1024)        // 256 f32
#define SMEM_SZ   (OFF_XW1 + 1024)

// per-quarter named barrier (ids 1..4, 128 threads each)
#define QBAR(grp) asm volatile("bar.sync %0, %1;" :: "r"((grp) + 1), "r"(128) : "memory")

// phase stagger: spin ~lim cycles (deterministic output; graph-safe)
__device__ __forceinline__ void stagger(u32 lim) {
    if (!lim) return;
    u32 t0 = (u32)clock();
    while ((u32)clock() - t0 < lim) { }
}

// ---- activations ----
__device__ __forceinline__ float tanh_hw(float x) {
    float y; asm("tanh.approx.f32 %0, %1;" : "=f"(y) : "f"(x)); return y;
}
__device__ __forceinline__ float sigm(float x) {
    return fmaf(0.5f, tanh_hw(0.5f * x), 0.5f);
}

// ---- mma / ldmatrix wrappers ----
__device__ __forceinline__ void mma16816(float* d, const u32* a, u32 b0, u32 b1) {
    asm("mma.sync.aligned.m16n8k16.row.col.f32.bf16.bf16.f32 "
        "{%0,%1,%2,%3}, {%4,%5,%6,%7}, {%8,%9}, {%0,%1,%2,%3};"
        : "+f"(d[0]), "+f"(d[1]), "+f"(d[2]), "+f"(d[3])
        : "r"(a[0]), "r"(a[1]), "r"(a[2]), "r"(a[3]), "r"(b0), "r"(b1));
}
__device__ __forceinline__ void ldm4(u32* r, u32 addr) {
    asm volatile("ldmatrix.sync.aligned.m8n8.x4.shared.b16 {%0,%1,%2,%3}, [%4];"
        : "=r"(r[0]), "=r"(r[1]), "=r"(r[2]), "=r"(r[3]) : "r"(addr));
}

__device__ __forceinline__ void split2(float v, unsigned short& hb, unsigned short& lb) {
    __nv_bfloat16 hi = __float2bfloat16_rn(v);
    __nv_bfloat16 lo = __float2bfloat16_rn(v - __bfloat162float(hi));
    hb = __bfloat16_as_ushort(hi);
    lb = __bfloat16_as_ushort(lo);
}

// Build B fragments (exact mma layout), 4 k-steps, K=64 weights only.
// phase 0 = encoder W_hh; phase 1 = decoder W_ih + W_hh fused.
__device__ void build_bfrag(char* sm, int tid, int phase,
        const float* __restrict__ W, const float* __restrict__ W2)
{
    u64* bhi = (u64*)(sm + OFF_BHI);
    u64* blo = (u64*)(sm + OFF_BLO);
    for (int idx = tid; idx < 4096; idx += NTH) {
        int ks = idx >> 10, wn = (idx >> 8) & 3, na = (idx >> 5) & 7, T = idx & 31;
        int cc = T >> 2, tq = T & 3;
        int unit = wn * 16 + ((cc >> 1) << 2) + (na >> 1);
        int gate = ((na & 1) << 1) | (cc & 1);
        int grow = gate * 64 + unit;
        u32 phi[2] = {0, 0}, plo[2] = {0, 0};
        #pragma unroll
        for (int i = 0; i < 2; i++)
            #pragma unroll
            for (int e = 0; e < 2; e++) {
                int k = ks * 16 + tq * 2 + e + 8 * i;
                float v = phase ? (W[grow*64+k] + W2[grow*64+k]) : W[grow*64+k];
                unsigned short hb, lb;
                split2(v, hb, lb);
                phi[i] |= (u32)hb << (16 * e);
                plo[i] |= (u32)lb << (16 * e);
            }
        bhi[idx] = (u64)phi[0] | ((u64)phi[1] << 32);
        blo[idx] = (u64)plo[0] | ((u64)plo[1] << 32);
    }
}

// decoder output: quarter-local; pair (t,t^1) splits one 64-dot, shfl-combined
__device__ __forceinline__ void emit_out(char* sm, int tid, int buf, int b0, int Btot,
                                         float* __restrict__ out, int tstep) {
    const int grp = tid >> 7;
    const int loc = tid & 127;
    const int hd  = loc & 1, p = loc >> 1;
    const int row = grp * 32 + (p >> 1), j = p & 1;
    const __nv_bfloat162* ph = (const __nv_bfloat162*)(sm + OFF_HA + buf*HA_BUF + row*AROW*2);
    const __nv_bfloat162* pl = (const __nv_bfloat162*)((const char*)ph + HA_PART);
    const float2* wp2 = (const float2*)((const float*)(sm + OFF_WPOS) + j*64);
    float a = 0.f;
    #pragma unroll
    for (int i = 0; i < 16; i++) {
        int u2 = hd * 16 + i;
        __nv_bfloat162 hv = ph[u2], lv = pl[u2];
        float2 w = wp2[u2];
        a += (__bfloat162float(hv.x) + __bfloat162float(lv.x)) * w.x
           + (__bfloat162float(hv.y) + __bfloat162float(lv.y)) * w.y;
    }
    a += __shfl_xor_sync(0xFFFFFFFFu, a, 1);
    if (hd == 0 && b0 + row < Btot)
        out[(size_t)(b0 + row) * (2*DEC_T) + tstep*2 + j]
            = a + ((const float*)(sm + OFF_BPOS))[j];
}

__global__ void __launch_bounds__(NTH, 1)
lstm_mma(const float* __restrict__ traj,
         const float* __restrict__ Wih_e, const float* __restrict__ Whh_e,
         const float* __restrict__ bih_e, const float* __restrict__ bhh_e,
         const float* __restrict__ Wih_d, const float* __restrict__ Whh_d,
         const float* __restrict__ bih_d, const float* __restrict__ bhh_d,
         const float* __restrict__ Wpos,  const float* __restrict__ bpos,
         float* __restrict__ out, int Btot)
{
    extern __shared__ char sm[];
    const int tid  = threadIdx.x;
    const int lane = tid & 31, warp = tid >> 5;
    const int grp  = warp >> 2;                 // quarter: rows grp*32 .. grp*32+31
    const int wn   = warp & 3;                  // n-band (units wn*16)
    const int rowbase = grp * 32;
    const int quad = lane >> 2, tq = lane & 3;
    const int b0   = blockIdx.x * TB;

    // ---------------- setup (global) ----------------
    build_bfrag(sm, tid, 0, Whh_e, (const float*)0);

    // tables: bias (encoder) + x-weight columns, col-id mapping i -> grow
    {
        float* btab = (float*)(sm + OFF_BTAB);
        float* xw0  = (float*)(sm + OFF_XW0);
        float* xw1  = (float*)(sm + OFF_XW1);
        for (int i = tid; i < 256; i += NTH) {
            int wn_ = i >> 6, tq_ = (i >> 4) & 3, na_ = (i >> 1) & 7, par = i & 1;
            int unit = wn_*16 + tq_*4 + (na_ >> 1);
            int gate = ((na_ & 1) << 1) | par;
            int grow = gate * 64 + unit;
            btab[i] = bih_e[grow] + bhh_e[grow];
            xw0[i]  = Wih_e[grow*2 + 0];
            xw1[i]  = Wih_e[grow*2 + 1];
        }
    }
    {   // x staging: xs[row*XROW + t*2 + sel]
        float* xs = (float*)(sm + OFF_X);
        for (int i = tid; i < TB * 2 * ENC_T; i += NTH) {
            int row = i / 40, r = i % 40;
            xs[row*XROW + r] = (b0 + row < Btot) ? traj[(size_t)b0 * 40 + i] : 0.f;
        }
    }
    // zero h cols 0-63 of buf0 (both parts)
    for (int i = tid; i < 2 * 128 * 64; i += NTH) {
        int col = i & 63, row = (i >> 6) & 127, part = i >> 13;
        *(unsigned short*)(sm + OFF_HA + part*HA_PART + (row*AROW + col)*2) = 0;
    }
    if (tid < 128) ((float*)(sm + OFF_WPOS))[tid] = Wpos[tid];
    if (tid < 2)   ((float*)(sm + OFF_BPOS))[tid] = bpos[tid];

    float c[2][2][4];
    #pragma unroll
    for (int a = 0; a < 2; a++)
        #pragma unroll
        for (int h = 0; h < 2; h++)
            #pragma unroll
            for (int m = 0; m < 4; m++) c[a][h][m] = 0.f;

    const u32 smbase = (u32)__cvta_generic_to_shared(sm);
    const int lrow = (lane & 7) + ((lane >> 3) & 1) * 8;
    const u32 ldm0 = (u32)(((rowbase + lrow) * AROW + (lane >> 4) * 8) * 2);

    __syncthreads();

    // phase-stagger the 4 groups so their MUFU epilogues interleave with
    // other groups' HMMA on each SMSP (offsets persist: identical per-step work)
    stagger((u32)grp * STAG);

    // ================ encoder: 20 steps (K=64 + fp32 x/bias init) ================
    for (int s = 0; s < ENC_T; s++) {
        const int rbuf = s & 1, wbuf = rbuf ^ 1;

        float acc[2][8][4];
        {   // acc init: bias + x_s @ Wx  (fp32, exact)
            const float4* bt4 = (const float4*)((const float*)(sm + OFF_BTAB) + ((wn*4 + tq) << 4));
            const float4* w04 = (const float4*)((const float*)(sm + OFF_XW0)  + ((wn*4 + tq) << 4));
            const float4* w14 = (const float4*)((const float*)(sm + OFF_XW1)  + ((wn*4 + tq) << 4));
            float bvv[16], w0v[16], w1v[16];
            #pragma unroll
            for (int q4 = 0; q4 < 4; q4++) {
                *(float4*)(bvv + 4*q4) = bt4[q4];
                *(float4*)(w0v + 4*q4) = w04[q4];
                *(float4*)(w1v + 4*q4) = w14[q4];
            }
            const float* xs = (const float*)(sm + OFF_X);
            float xv0[2][2], xv1[2][2];
            #pragma unroll
            for (int ma = 0; ma < 2; ma++)
                #pragma unroll
                for (int hh = 0; hh < 2; hh++) {
                    int row = rowbase + ma*16 + quad + hh*8;
                    xv0[ma][hh] = xs[row*XROW + 2*s];
                    xv1[ma][hh] = xs[row*XROW + 2*s + 1];
                }
            #pragma unroll
            for (int ma = 0; ma < 2; ma++)
                #pragma unroll
                for (int na = 0; na < 8; na++)
                    #pragma unroll
                    for (int hh = 0; hh < 2; hh++)
                        #pragma unroll
                        for (int par = 0; par < 2; par++) {
                            int cix = na*2 + par;
                            acc[ma][na][hh*2+par] =
                                fmaf(xv1[ma][hh], w1v[cix],
                                fmaf(xv0[ma][hh], w0v[cix], bvv[cix]));
                        }
        }

        const u32 ha_hi = smbase + OFF_HA + (u32)rbuf * HA_BUF + ldm0;
        const u64* __restrict__ bhi = (const u64*)(sm + OFF_BHI);
        const u64* __restrict__ blo = (const u64*)(sm + OFF_BLO);

        #pragma unroll
        for (int ks = 0; ks < 4; ks++) {
            const int bix = ((ks * 4 + wn) * 8) * 32 + lane;
            u32 ahi0[4], ahi1[4], alo0[4], alo1[4];
            ldm4(ahi0, ha_hi + (u32)((ks*16) * 2));
            ldm4(ahi1, ha_hi + (u32)((16*AROW + ks*16) * 2));
            ldm4(alo0, ha_hi + HA_PART + (u32)((ks*16) * 2));
            ldm4(alo1, ha_hi + HA_PART + (u32)((16*AROW + ks*16) * 2));
            #pragma unroll
            for (int na = 0; na < 8; na++) {
                u64 vh = bhi[bix + na*32], vl = blo[bix + na*32];
                u32 bh0 = (u32)vh, bh1 = (u32)(vh >> 32);
                u32 bl0 = (u32)vl, bl1 = (u32)(vl >> 32);
                mma16816(acc[0][na], ahi0, bh0, bh1);
                mma16816(acc[1][na], ahi1, bh0, bh1);
                mma16816(acc[0][na], ahi0, bl0, bl1);
                mma16816(acc[1][na], ahi1, bl0, bl1);
                mma16816(acc[0][na], alo0, bh0, bh1);
                mma16816(acc[1][na], alo1, bh0, bh1);
            }
        }

        #pragma unroll
        for (int ma = 0; ma < 2; ma++)
            #pragma unroll
            for (int hh = 0; hh < 2; hh++) {
                unsigned short hb[4], lb[4];
                #pragma unroll
                for (int m = 0; m < 4; m++) {
                    float gi = acc[ma][2*m  ][hh*2 + 0];
                    float gf = acc[ma][2*m  ][hh*2 + 1];
                    float gg = acc[ma][2*m+1][hh*2 + 0];
                    float go = acc[ma][2*m+1][hh*2 + 1];
                    float cn = sigm(gf) * c[ma][hh][m] + sigm(gi) * tanh_hw(gg);
                    c[ma][hh][m] = cn;
                    split2(sigm(go) * tanh_hw(cn), hb[m], lb[m]);
                }
                int row  = rowbase + ma*16 + quad + hh*8;
                int colb = (wn*16 + tq*4) * 2;
                char* ph = sm + OFF_HA + wbuf*HA_BUF + row*AROW*2 + colb;
                uint2 vhi, vlo;
                vhi.x = (u32)hb[0] | ((u32)hb[1] << 16);
                vhi.y = (u32)hb[2] | ((u32)hb[3] << 16);
                vlo.x = (u32)lb[0] | ((u32)lb[1] << 16);
                vlo.y = (u32)lb[2] | ((u32)lb[3] << 16);
                *(uint2*)ph             = vhi;
                *(uint2*)(ph + HA_PART) = vlo;
            }
        QBAR(grp);
    }

    // ---- decoder transition (global): rebuild B fused + decoder bias table ----
    __syncthreads();
    build_bfrag(sm, tid, 1, Wih_d, Whh_d);
    {
        float* btab = (float*)(sm + OFF_BTAB);
        for (int i = tid; i < 256; i += NTH) {
            int wn_ = i >> 6, tq_ = (i >> 4) & 3, na_ = (i >> 1) & 7, par = i & 1;
            int unit = wn_*16 + tq_*4 + (na_ >> 1);
            int gate = ((na_ & 1) << 1) | par;
            int grow = gate * 64 + unit;
            btab[i] = bih_d[grow] + bhh_d[grow];
        }
    }
    __syncthreads();

    // re-stagger (the global syncs above re-aligned the groups)
    stagger((u32)grp * STAG);

    // ================ decoder: 30 steps (K=64, bias in acc) ================
    for (int d = 0; d < DEC_T; d++) {
        const int s = ENC_T + d;
        const int rbuf = s & 1, wbuf = rbuf ^ 1;

        if (d >= 1) emit_out(sm, tid, rbuf, b0, Btot, out, d - 1);

        float acc[2][8][4];
        {
            const float4* bt4 = (const float4*)((const float*)(sm + OFF_BTAB) + ((wn*4 + tq) << 4));
            float bvv[16];
            #pragma unroll
            for (int q4 = 0; q4 < 4; q4++) *(float4*)(bvv + 4*q4) = bt4[q4];
            #pragma unroll
            for (int na = 0; na < 8; na++) {
                float b0v = bvv[na*2], b1v = bvv[na*2+1];
                acc[0][na][0] = b0v; acc[0][na][1] = b1v;
                acc[0][na][2] = b0v; acc[0][na][3] = b1v;
                acc[1][na][0] = b0v; acc[1][na][1] = b1v;
                acc[1][na][2] = b0v; acc[1][na][3] = b1v;
            }
        }

        const u32 ha_hi = smbase + OFF_HA + (u32)rbuf * HA_BUF + ldm0;
        const u64* __restrict__ bhi = (const u64*)(sm + OFF_BHI);
        const u64* __restrict__ blo = (const u64*)(sm + OFF_BLO);

        #pragma unroll
        for (int ks = 0; ks < 4; ks++) {
            const int bix = ((ks * 4 + wn) * 8) * 32 + lane;
            u32 ahi0[4], ahi1[4], alo0[4], alo1[4];
            ldm4(ahi0, ha_hi + (u32)((ks*16) * 2));
            ldm4(ahi1, ha_hi + (u32)((16*AROW + ks*16) * 2));
            ldm4(alo0, ha_hi + HA_PART + (u32)((ks*16) * 2));
            ldm4(alo1, ha_hi + HA_PART + (u32)((16*AROW + ks*16) * 2));
            #pragma unroll
            for (int na = 0; na < 8; na++) {
                u64 vh = bhi[bix + na*32], vl = blo[bix + na*32];
                u32 bh0 = (u32)vh, bh1 = (u32)(vh >> 32);
                u32 bl0 = (u32)vl, bl1 = (u32)(vl >> 32);
                mma16816(acc[0][na], ahi0, bh0, bh1);
                mma16816(acc[1][na], ahi1, bh0, bh1);
                mma16816(acc[0][na], ahi0, bl0, bl1);
                mma16816(acc[1][na], ahi1, bl0, bl1);
                mma16816(acc[0][na], alo0, bh0, bh1);
                mma16816(acc[1][na], alo1, bh0, bh1);
            }
        }

        #pragma unroll
        for (int ma = 0; ma < 2; ma++)
            #pragma unroll
            for (int hh = 0; hh < 2; hh++) {
                unsigned short hb[4], lb[4];
                #pragma unroll
                for (int m = 0; m < 4; m++) {
                    float gi = acc[ma][2*m  ][hh*2 + 0];
                    float gf = acc[ma][2*m  ][hh*2 + 1];
                    float gg = acc[ma][2*m+1][hh*2 + 0];
                    float go = acc[ma][2*m+1][hh*2 + 1];
                    float cn = sigm(gf) * c[ma][hh][m] + sigm(gi) * tanh_hw(gg);
                    c[ma][hh][m] = cn;
                    split2(sigm(go) * tanh_hw(cn), hb[m], lb[m]);
                }
                int row  = rowbase + ma*16 + quad + hh*8;
                int colb = (wn*16 + tq*4) * 2;
                char* ph = sm + OFF_HA + wbuf*HA_BUF + row*AROW*2 + colb;
                uint2 vhi, vlo;
                vhi.x = (u32)hb[0] | ((u32)hb[1] << 16);
                vhi.y = (u32)hb[2] | ((u32)hb[3] << 16);
                vlo.x = (u32)lb[0] | ((u32)lb[1] << 16);
                vlo.y = (u32)lb[2] | ((u32)lb[3] << 16);
                *(uint2*)ph             = vhi;
                *(uint2*)(ph + HA_PART) = vlo;
            }
        QBAR(grp);
    }

    // final output (h_29 lives in buf[TOT_T & 1] = buf0)
    emit_out(sm, tid, TOT_T & 1, b0, Btot, out, DEC_T - 1);
}

extern "C" void kernel_launch(void* const* d_in, const int* in_sizes, int n_in,
                              void* d_out, int out_size) {
    const float* traj  = (const float*)d_in[0];
    const float* Wih_e = (const float*)d_in[1];
    const float* Whh_e = (const float*)d_in[2];
    const float* bih_e = (const float*)d_in[3];
    const float* bhh_e = (const float*)d_in[4];
    const float* Wih_d = (const float*)d_in[5];
    const float* Whh_d = (const float*)d_in[6];
    const float* bih_d = (const float*)d_in[7];
    const float* bhh_d = (const float*)d_in[8];
    const float* Wpos  = (const float*)d_in[9];
    const float* bpos  = (const float*)d_in[10];
    float* out = (float*)d_out;

    int B = in_sizes[0] / (2 * ENC_T);
    int grid = (B + TB - 1) / TB;

    cudaFuncSetAttribute(lstm_mma,
                         cudaFuncAttributeMaxDynamicSharedMemorySize, SMEM_SZ);

    lstm_mma<<<grid, NTH, SMEM_SZ>>>(traj, Wih_e, Whh_e, bih_e, bhh_e,
                                     Wih_d, Whh_d, bih_d, bhh_d,
                                     Wpos, bpos, out, B);
}